// round 8
// baseline (speedup 1.0000x reference)
#include <cuda_runtime.h>
#include <math.h>

// Problem constants (fixed shapes from reference)
#define B_    4
#define S_    4096
#define H_    16
#define D_    128
#define HALF_ 64
#define MAX_OFFSET_ 512

// inv_freq passed by value (constant space), computed on host in double.
struct InvFreq { float v[HALF_]; };

// One block per (b, s) position. 256 threads.
//  - threads 0..63 compute the 64 cos/sin pairs for this position into smem
//    (identical numerics to the reference path: fp32 inv_freq, fp32 mul,
//    accurate sincosf).
//  - then each thread owns float4-pair j = tid&15 of three rows:
//    r = tid>>4 (q), r+16 (k), r+32 (v). 6 front-batched LDG.128, fully
//    coalesced 128B transactions, branch-free type dispatch.
// qkv/out are zero-reuse streams -> evict-first (.cs).
__global__ void __launch_bounds__(256) rope_fused_kernel(
    const float4* __restrict__ qkv,
    const int*    __restrict__ offsets,
    float4*       __restrict__ out,
    InvFreq       inv)
{
    __shared__ __align__(16) float scos[HALF_];
    __shared__ __align__(16) float ssin[HALF_];

    int bs  = blockIdx.x;          // b*S + s
    int tid = threadIdx.x;

    if (tid < HALF_) {
        int b   = bs >> 12;        // S = 4096
        int s   = bs & (S_ - 1);
        int pos = offsets[b] + s;
        float freq = (float)pos * inv.v[tid];
        float sn, c;
        sincosf(freq, &sn, &c);
        scos[tid] = c;
        ssin[tid] = sn;
    }
    __syncthreads();

    int j = tid & 15;              // float4 index within the half
    int r = tid >> 4;              // head row within q-group [0,16)

    // float4 offsets: position block = 48 rows * 32 float4 = 1536
    long base  = (long)bs * 1536;
    long qoff  = base + (long)r * 32 + j;        // q row
    long koff  = qoff + 16 * 32;                 // k row (r+16)
    long voff  = qoff + 32 * 32;                 // v row (r+32)

    // Front-batch all 6 loads (MLP=6)
    float4 q1 = __ldcs(&qkv[qoff]);
    float4 q2 = __ldcs(&qkv[qoff + 16]);
    float4 k1 = __ldcs(&qkv[koff]);
    float4 k2 = __ldcs(&qkv[koff + 16]);
    float4 v1 = __ldcs(&qkv[voff]);
    float4 v2 = __ldcs(&qkv[voff + 16]);

    float4 c  = reinterpret_cast<const float4*>(scos)[j];
    float4 sn = reinterpret_cast<const float4*>(ssin)[j];

    float4 o1, o2;
    // q rotate
    o1.x = fmaf(q1.x, c.x, -q2.x * sn.x);
    o1.y = fmaf(q1.y, c.y, -q2.y * sn.y);
    o1.z = fmaf(q1.z, c.z, -q2.z * sn.z);
    o1.w = fmaf(q1.w, c.w, -q2.w * sn.w);
    o2.x = fmaf(q1.x, sn.x, q2.x * c.x);
    o2.y = fmaf(q1.y, sn.y, q2.y * c.y);
    o2.z = fmaf(q1.z, sn.z, q2.z * c.z);
    o2.w = fmaf(q1.w, sn.w, q2.w * c.w);
    __stcs(&out[qoff],      o1);
    __stcs(&out[qoff + 16], o2);

    // k rotate
    o1.x = fmaf(k1.x, c.x, -k2.x * sn.x);
    o1.y = fmaf(k1.y, c.y, -k2.y * sn.y);
    o1.z = fmaf(k1.z, c.z, -k2.z * sn.z);
    o1.w = fmaf(k1.w, c.w, -k2.w * sn.w);
    o2.x = fmaf(k1.x, sn.x, k2.x * c.x);
    o2.y = fmaf(k1.y, sn.y, k2.y * c.y);
    o2.z = fmaf(k1.z, sn.z, k2.z * c.z);
    o2.w = fmaf(k1.w, sn.w, k2.w * c.w);
    __stcs(&out[koff],      o1);
    __stcs(&out[koff + 16], o2);

    // v copy
    __stcs(&out[voff],      v1);
    __stcs(&out[voff + 16], v2);
}

extern "C" void kernel_launch(void* const* d_in, const int* in_sizes, int n_in,
                              void* d_out, int out_size) {
    const float4* qkv     = (const float4*)d_in[0];
    const int*    offsets = (const int*)d_in[1];
    float4*       out     = (float4*)d_out;

    // Host-side inv_freq: double precision, rounded to fp32 (same numerics
    // as before). Deterministic; 64 floats passed by value.
    InvFreq inv;
    for (int i = 0; i < HALF_; i++) {
        inv.v[i] = (float)exp(-log(10000.0) * ((double)i / 64.0));
    }

    rope_fused_kernel<<<B_ * S_, 256>>>(qkv, offsets, out, inv);
}

// round 9
// speedup vs baseline: 1.0118x; 1.0118x over previous
#include <cuda_runtime.h>
#include <math.h>

// Problem constants (fixed shapes from reference)
#define B_    4
#define S_    4096
#define H_    16
#define D_    128
#define HALF_ 64
#define MAX_OFFSET_ 512

// inv_freq passed by value (constant space), computed on host in double.
struct InvFreq { float v[HALF_]; };

// One block per (b, s) position. 256 threads, NO smem, NO __syncthreads.
// Warp-local cos/sin: lane l computes sincosf for freq indices {2l, 2l+1};
// lane with j = lane&15 gathers c/s[4j..4j+3] from lanes 2j and 2j+1 via
// 8 shuffles. Warps are fully independent -> loads issue immediately.
// Each thread owns float4-pair j of rows r (q), r+16 (k), r+32 (v) where
// r = tid>>4: 6 front-batched LDG.128, fully coalesced, branch-free.
// qkv/out are zero-reuse streams -> evict-first (.cs).
__global__ void __launch_bounds__(256) rope_fused_kernel(
    const float4* __restrict__ qkv,
    const int*    __restrict__ offsets,
    float4*       __restrict__ out,
    InvFreq       inv)
{
    int bs   = blockIdx.x;           // b*S + s
    int tid  = threadIdx.x;
    int lane = tid & 31;
    int j    = tid & 15;             // float4 index within the half
    int r    = tid >> 4;             // head row within q-group [0,16)

    // float4 offsets: position block = 48 rows * 32 float4 = 1536
    long base = (long)bs * 1536;
    long qoff = base + (long)r * 32 + j;         // q row
    long koff = qoff + 16 * 32;                  // k row (r+16)
    long voff = qoff + 32 * 32;                  // v row (r+32)

    // Front-batch all 6 loads (MLP=6) BEFORE the sincos math
    float4 q1 = __ldcs(&qkv[qoff]);
    float4 q2 = __ldcs(&qkv[qoff + 16]);
    float4 k1 = __ldcs(&qkv[koff]);
    float4 k2 = __ldcs(&qkv[koff + 16]);
    float4 v1 = __ldcs(&qkv[voff]);
    float4 v2 = __ldcs(&qkv[voff + 16]);

    // Per-warp cos/sin (identical numerics to reference: fp32 inv_freq,
    // fp32 pos*inv, accurate sincosf)
    int b   = bs >> 12;              // S = 4096
    int s   = bs & (S_ - 1);
    float fpos = (float)(offsets[b] + s);

    float c_lo, s_lo, c_hi, s_hi;
    sincosf(fpos * inv.v[2 * lane],     &s_lo, &c_lo);
    sincosf(fpos * inv.v[2 * lane + 1], &s_hi, &c_hi);

    const unsigned FULL = 0xFFFFFFFFu;
    int l0 = 2 * j, l1 = 2 * j + 1;
    float4 c, sn;
    c.x  = __shfl_sync(FULL, c_lo, l0);
    c.y  = __shfl_sync(FULL, c_hi, l0);
    c.z  = __shfl_sync(FULL, c_lo, l1);
    c.w  = __shfl_sync(FULL, c_hi, l1);
    sn.x = __shfl_sync(FULL, s_lo, l0);
    sn.y = __shfl_sync(FULL, s_hi, l0);
    sn.z = __shfl_sync(FULL, s_lo, l1);
    sn.w = __shfl_sync(FULL, s_hi, l1);

    float4 o1, o2;
    // q rotate
    o1.x = fmaf(q1.x, c.x, -q2.x * sn.x);
    o1.y = fmaf(q1.y, c.y, -q2.y * sn.y);
    o1.z = fmaf(q1.z, c.z, -q2.z * sn.z);
    o1.w = fmaf(q1.w, c.w, -q2.w * sn.w);
    o2.x = fmaf(q1.x, sn.x, q2.x * c.x);
    o2.y = fmaf(q1.y, sn.y, q2.y * c.y);
    o2.z = fmaf(q1.z, sn.z, q2.z * c.z);
    o2.w = fmaf(q1.w, sn.w, q2.w * c.w);
    __stcs(&out[qoff],      o1);
    __stcs(&out[qoff + 16], o2);

    // k rotate
    o1.x = fmaf(k1.x, c.x, -k2.x * sn.x);
    o1.y = fmaf(k1.y, c.y, -k2.y * sn.y);
    o1.z = fmaf(k1.z, c.z, -k2.z * sn.z);
    o1.w = fmaf(k1.w, c.w, -k2.w * sn.w);
    o2.x = fmaf(k1.x, sn.x, k2.x * c.x);
    o2.y = fmaf(k1.y, sn.y, k2.y * c.y);
    o2.z = fmaf(k1.z, sn.z, k2.z * c.z);
    o2.w = fmaf(k1.w, sn.w, k2.w * c.w);
    __stcs(&out[koff],      o1);
    __stcs(&out[koff + 16], o2);

    // v copy
    __stcs(&out[voff],      v1);
    __stcs(&out[voff + 16], v2);
}

extern "C" void kernel_launch(void* const* d_in, const int* in_sizes, int n_in,
                              void* d_out, int out_size) {
    const float4* qkv     = (const float4*)d_in[0];
    const int*    offsets = (const int*)d_in[1];
    float4*       out     = (float4*)d_out;

    // Host-side inv_freq: double precision, rounded to fp32 (same numerics
    // as before). Deterministic; 64 floats passed by value.
    InvFreq inv;
    for (int i = 0; i < HALF_; i++) {
        inv.v[i] = (float)exp(-log(10000.0) * ((double)i / 64.0));
    }

    rope_fused_kernel<<<B_ * S_, 256>>>(qkv, offsets, out, inv);
}

// round 10
// speedup vs baseline: 1.0129x; 1.0011x over previous
#include <cuda_runtime.h>
#include <math.h>

// Problem constants (fixed shapes from reference)
#define B_    4
#define S_    4096
#define H_    16
#define D_    128
#define HALF_ 64
#define MAX_OFFSET_ 512

// inv_freq passed by value (constant space), computed on host in double.
struct InvFreq { float v[HALF_]; };

// One block per TWO consecutive (b, s) positions. 256 threads, no smem/sync.
// Each thread owns float4-pair j = tid&15 of rows r (q), r+16 (k), r+32 (v),
// r = tid>>4, for BOTH positions: 12 front-batched LDG.128 (MLP=12) to keep
// DRAM queues full through read/write turnarounds.
// Warp-local cos/sin per position via 2 sincosf + 8 shuffles (identical
// numerics to reference: fp32 inv_freq, fp32 pos*inv, accurate sincosf).
// qkv/out are zero-reuse streams -> evict-first (.cs).
__global__ void __launch_bounds__(256) rope_fused2_kernel(
    const float4* __restrict__ qkv,
    const int*    __restrict__ offsets,
    float4*       __restrict__ out,
    InvFreq       inv)
{
    int bs0  = blockIdx.x << 1;      // first position (b*S + s), pair-aligned
    int tid  = threadIdx.x;
    int lane = tid & 31;
    int j    = tid & 15;             // float4 index within the half
    int r    = tid >> 4;             // head row within q-group [0,16)

    // float4 offsets: position block = 48 rows * 32 float4 = 1536
    // max index = 16384*1536 + 1535 < 2^31 -> 32-bit indexing is safe.
    int qoff0 = bs0 * 1536 + r * 32 + j;  // q row, pos0
    int koff0 = qoff0 + 16 * 32;          // k row
    int voff0 = qoff0 + 32 * 32;          // v row
    int qoff1 = qoff0 + 1536;             // same rows, pos1
    int koff1 = koff0 + 1536;
    int voff1 = voff0 + 1536;

    // Front-batch all 12 loads (MLP=12) before any math
    float4 q1a = __ldcs(&qkv[qoff0]);
    float4 q2a = __ldcs(&qkv[qoff0 + 16]);
    float4 k1a = __ldcs(&qkv[koff0]);
    float4 k2a = __ldcs(&qkv[koff0 + 16]);
    float4 v1a = __ldcs(&qkv[voff0]);
    float4 v2a = __ldcs(&qkv[voff0 + 16]);
    float4 q1b = __ldcs(&qkv[qoff1]);
    float4 q2b = __ldcs(&qkv[qoff1 + 16]);
    float4 k1b = __ldcs(&qkv[koff1]);
    float4 k2b = __ldcs(&qkv[koff1 + 16]);
    float4 v1b = __ldcs(&qkv[voff1]);
    float4 v2b = __ldcs(&qkv[voff1 + 16]);

    // Position bases
    int b    = bs0 >> 12;            // S = 4096; pair never crosses a batch
    int s0   = bs0 & (S_ - 1);
    int pos0 = offsets[b] + s0;

    const unsigned FULL = 0xFFFFFFFFu;
    int l0 = 2 * j, l1 = 2 * j + 1;
    float fi_lo = inv.v[2 * lane];
    float fi_hi = inv.v[2 * lane + 1];

    float4 o1, o2;

    // ---- position 0 ----
    {
        float fpos = (float)pos0;
        float c_lo, s_lo, c_hi, s_hi;
        sincosf(fpos * fi_lo, &s_lo, &c_lo);
        sincosf(fpos * fi_hi, &s_hi, &c_hi);
        float4 c, sn;
        c.x  = __shfl_sync(FULL, c_lo, l0);
        c.y  = __shfl_sync(FULL, c_hi, l0);
        c.z  = __shfl_sync(FULL, c_lo, l1);
        c.w  = __shfl_sync(FULL, c_hi, l1);
        sn.x = __shfl_sync(FULL, s_lo, l0);
        sn.y = __shfl_sync(FULL, s_hi, l0);
        sn.z = __shfl_sync(FULL, s_lo, l1);
        sn.w = __shfl_sync(FULL, s_hi, l1);

        o1.x = fmaf(q1a.x, c.x, -q2a.x * sn.x);
        o1.y = fmaf(q1a.y, c.y, -q2a.y * sn.y);
        o1.z = fmaf(q1a.z, c.z, -q2a.z * sn.z);
        o1.w = fmaf(q1a.w, c.w, -q2a.w * sn.w);
        o2.x = fmaf(q1a.x, sn.x, q2a.x * c.x);
        o2.y = fmaf(q1a.y, sn.y, q2a.y * c.y);
        o2.z = fmaf(q1a.z, sn.z, q2a.z * c.z);
        o2.w = fmaf(q1a.w, sn.w, q2a.w * c.w);
        __stcs(&out[qoff0],      o1);
        __stcs(&out[qoff0 + 16], o2);

        o1.x = fmaf(k1a.x, c.x, -k2a.x * sn.x);
        o1.y = fmaf(k1a.y, c.y, -k2a.y * sn.y);
        o1.z = fmaf(k1a.z, c.z, -k2a.z * sn.z);
        o1.w = fmaf(k1a.w, c.w, -k2a.w * sn.w);
        o2.x = fmaf(k1a.x, sn.x, k2a.x * c.x);
        o2.y = fmaf(k1a.y, sn.y, k2a.y * c.y);
        o2.z = fmaf(k1a.z, sn.z, k2a.z * c.z);
        o2.w = fmaf(k1a.w, sn.w, k2a.w * c.w);
        __stcs(&out[koff0],      o1);
        __stcs(&out[koff0 + 16], o2);

        __stcs(&out[voff0],      v1a);
        __stcs(&out[voff0 + 16], v2a);
    }

    // ---- position 1 ----
    {
        float fpos = (float)(pos0 + 1);
        float c_lo, s_lo, c_hi, s_hi;
        sincosf(fpos * fi_lo, &s_lo, &c_lo);
        sincosf(fpos * fi_hi, &s_hi, &c_hi);
        float4 c, sn;
        c.x  = __shfl_sync(FULL, c_lo, l0);
        c.y  = __shfl_sync(FULL, c_hi, l0);
        c.z  = __shfl_sync(FULL, c_lo, l1);
        c.w  = __shfl_sync(FULL, c_hi, l1);
        sn.x = __shfl_sync(FULL, s_lo, l0);
        sn.y = __shfl_sync(FULL, s_hi, l0);
        sn.z = __shfl_sync(FULL, s_lo, l1);
        sn.w = __shfl_sync(FULL, s_hi, l1);

        o1.x = fmaf(q1b.x, c.x, -q2b.x * sn.x);
        o1.y = fmaf(q1b.y, c.y, -q2b.y * sn.y);
        o1.z = fmaf(q1b.z, c.z, -q2b.z * sn.z);
        o1.w = fmaf(q1b.w, c.w, -q2b.w * sn.w);
        o2.x = fmaf(q1b.x, sn.x, q2b.x * c.x);
        o2.y = fmaf(q1b.y, sn.y, q2b.y * c.y);
        o2.z = fmaf(q1b.z, sn.z, q2b.z * c.z);
        o2.w = fmaf(q1b.w, sn.w, q2b.w * c.w);
        __stcs(&out[qoff1],      o1);
        __stcs(&out[qoff1 + 16], o2);

        o1.x = fmaf(k1b.x, c.x, -k2b.x * sn.x);
        o1.y = fmaf(k1b.y, c.y, -k2b.y * sn.y);
        o1.z = fmaf(k1b.z, c.z, -k2b.z * sn.z);
        o1.w = fmaf(k1b.w, c.w, -k2b.w * sn.w);
        o2.x = fmaf(k1b.x, sn.x, k2b.x * c.x);
        o2.y = fmaf(k1b.y, sn.y, k2b.y * c.y);
        o2.z = fmaf(k1b.z, sn.z, k2b.z * c.z);
        o2.w = fmaf(k1b.w, sn.w, k2b.w * c.w);
        __stcs(&out[koff1],      o1);
        __stcs(&out[koff1 + 16], o2);

        __stcs(&out[voff1],      v1b);
        __stcs(&out[voff1 + 16], v2b);
    }
}

extern "C" void kernel_launch(void* const* d_in, const int* in_sizes, int n_in,
                              void* d_out, int out_size) {
    const float4* qkv     = (const float4*)d_in[0];
    const int*    offsets = (const int*)d_in[1];
    float4*       out     = (float4*)d_out;

    // Host-side inv_freq: double precision, rounded to fp32 (same numerics
    // as before). Deterministic; 64 floats passed by value.
    InvFreq inv;
    for (int i = 0; i < HALF_; i++) {
        inv.v[i] = (float)exp(-log(10000.0) * ((double)i / 64.0));
    }

    rope_fused2_kernel<<<(B_ * S_) / 2, 256>>>(qkv, offsets, out, inv);
}